// round 7
// baseline (speedup 1.0000x reference)
#include <cuda_runtime.h>
#include <cstdint>

#define BB 16
#define NN 2048
#define HH 128
#define KNN 16
#define NSPLIT 4
#define SPLEN (NN / NSPLIT)   // 512

// ---------------- scratch (device globals; no allocs allowed) ----------------
__device__ int   g_nbr[BB * NN * KNN];              // final neighbor indices (batch-local)
__device__ float g_cd[BB * NN * NSPLIT * KNN];      // split candidates: distances
__device__ int   g_ci[BB * NN * NSPLIT * KNN];      // split candidates: indices
__device__ float g_h1[BB * NN * HH];
__device__ float g_h2[BB * NN * HH];
__device__ float g_WT[4 * HH * HH];                 // W2r^T, W2s^T, W3r^T, W3s^T (k-major)

// ---------------- packed fp32x2 helpers (Blackwell FFMA2 path) ----------------
__device__ __forceinline__ unsigned long long fma2(unsigned long long a,
                                                   unsigned long long b,
                                                   unsigned long long c) {
    unsigned long long d;
    asm("fma.rn.f32x2 %0, %1, %2, %3;" : "=l"(d) : "l"(a), "l"(b), "l"(c));
    return d;
}
__device__ __forceinline__ unsigned long long pk2(float lo, float hi) {
    unsigned long long d;
    asm("mov.b64 %0, {%1, %2};" : "=l"(d) : "r"(__float_as_uint(lo)), "r"(__float_as_uint(hi)));
    return d;
}
__device__ __forceinline__ void upk2(unsigned long long v, float& lo, float& hi) {
    unsigned int a, b;
    asm("mov.b64 {%0, %1}, %2;" : "=r"(a), "=r"(b) : "l"(v));
    lo = __uint_as_float(a);
    hi = __uint_as_float(b);
}

// ---------------- kNN phase 1: split-K brute force --------------------------
// grid (16 slices, 4 splits, 16 batches), block 128. One thread = one query,
// scanning a 512-candidate slice held in 8KB smem.
__global__ __launch_bounds__(128) void knn_split_kernel(const float* __restrict__ pts) {
    __shared__ float4 sp[SPLEN];   // (x, y, z, |p|^2) : 8KB
    const int b = blockIdx.z;
    const int j0 = blockIdx.y * SPLEN;
    const float* pb = pts + (size_t)b * NN * 3;

    for (int t = threadIdx.x; t < SPLEN; t += 128) {
        const int j = j0 + t;
        float x = pb[j * 3], y = pb[j * 3 + 1], z = pb[j * 3 + 2];
        sp[t] = make_float4(x, y, z, x * x + y * y + z * z);
    }
    __syncthreads();

    const int i = blockIdx.x * 128 + threadIdx.x;
    const float px = pb[i * 3], py = pb[i * 3 + 1], pz = pb[i * 3 + 2];
    const float pw = px * px + py * py + pz * pz;

    float bd[KNN];
    int   bi[KNN];
#pragma unroll
    for (int s = 0; s < KNN; s++) { bd[s] = 3.4e38f; bi[s] = 0; }
    float wv = 3.4e38f;

#pragma unroll 2
    for (int t = 0; t < SPLEN; t++) {
        float4 q = sp[t];
        float dot = px * q.x + py * q.y + pz * q.z;
        float d2 = pw + q.w - 2.0f * dot;
        if (d2 < wv) {
            bool done = false;
#pragma unroll
            for (int s = 0; s < KNN; s++) {
                if (!done && bd[s] == wv) { bd[s] = d2; bi[s] = j0 + t; done = true; }
            }
            wv = bd[0];
#pragma unroll
            for (int s = 1; s < KNN; s++) wv = fmaxf(wv, bd[s]);
        }
    }

    const size_t o = (((size_t)b * NN + i) * NSPLIT + blockIdx.y) * KNN;
#pragma unroll
    for (int s = 0; s < KNN; s++) { g_cd[o + s] = bd[s]; g_ci[o + s] = bi[s]; }
}

// ---------------- kNN phase 2: merge 64 -> 16 per query ---------------------
// grid 128, block 256. One thread per query.
__global__ __launch_bounds__(256) void knn_merge_kernel() {
    const int q = blockIdx.x * 256 + threadIdx.x;   // 0..32767
    const float* cd = g_cd + (size_t)q * (NSPLIT * KNN);
    const int*   ci = g_ci + (size_t)q * (NSPLIT * KNN);

    float bd[KNN];
    int   bi[KNN];
#pragma unroll
    for (int s = 0; s < KNN; s++) { bd[s] = 3.4e38f; bi[s] = 0; }
    float wv = 3.4e38f;

    for (int t = 0; t < NSPLIT * KNN; t++) {
        float d2 = cd[t];
        if (d2 < wv) {
            int j = ci[t];
            bool done = false;
#pragma unroll
            for (int s = 0; s < KNN; s++) {
                if (!done && bd[s] == wv) { bd[s] = d2; bi[s] = j; done = true; }
            }
            wv = bd[0];
#pragma unroll
            for (int s = 1; s < KNN; s++) wv = fmaxf(wv, bd[s]);
        }
    }

    int* o = g_nbr + (size_t)q * KNN;
#pragma unroll
    for (int s = 0; s < KNN; s++) o[s] = bi[s];
}

// ---------------- layer 1 (input dim 3): 1 thread per point ------------------
// grid 128, block 256.
__global__ __launch_bounds__(256) void layer1_kernel(const float* __restrict__ pts,
                                                     const float* __restrict__ W1r,
                                                     const float* __restrict__ b1,
                                                     const float* __restrict__ W1s) {
    __shared__ float sWr[HH * 3], sWs[HH * 3], sb[HH];
    const int tid = threadIdx.x;
    for (int t = tid; t < HH * 3; t += 256) { sWr[t] = W1r[t]; sWs[t] = W1s[t]; }
    if (tid < 128) sb[tid] = b1[tid];
    __syncthreads();

    const int i = blockIdx.x * 256 + tid;
    const int base = (i >> 11) << 11;

    const float* xp = pts + (size_t)i * 3;
    const float x0 = xp[0], x1 = xp[1], x2 = xp[2];

    float a0 = 0.f, a1 = 0.f, a2 = 0.f;
    const int* nb = g_nbr + (size_t)i * KNN;
#pragma unroll
    for (int n = 0; n < KNN; n++) {
        int j = nb[n];
        const float* c = pts + (size_t)(base + j) * 3;
        a0 += c[0]; a1 += c[1]; a2 += c[2];
    }

    float* orow = g_h1 + (size_t)i * HH;
#pragma unroll 2
    for (int h = 0; h < HH; h += 4) {
        float4 v;
        float* vv = (float*)&v;
#pragma unroll
        for (int e = 0; e < 4; e++) {
            int hh = h + e;
            float s = sb[hh]
                    + sWr[hh * 3 + 0] * a0 + sWr[hh * 3 + 1] * a1 + sWr[hh * 3 + 2] * a2
                    + sWs[hh * 3 + 0] * x0 + sWs[hh * 3 + 1] * x1 + sWs[hh * 3 + 2] * x2;
            vv[e] = fmaxf(s, 0.0f);
        }
        *(float4*)(orow + h) = v;
    }
}

// ---------------- W transpose (k-major for coalesced GEMM staging) -----------
// grid (64, 4), block 256
__global__ __launch_bounds__(256) void transpose_kernel(const float* __restrict__ W2r,
                                                        const float* __restrict__ W2s,
                                                        const float* __restrict__ W3r,
                                                        const float* __restrict__ W3s) {
    const float* src[4] = {W2r, W2s, W3r, W3s};
    int m = blockIdx.y;
    int idx = blockIdx.x * 256 + threadIdx.x;   // 0..16383
    int k = idx >> 7, h = idx & 127;
    g_WT[m * HH * HH + k * HH + h] = src[m][h * HH + k];
}

// ---------------- layers 2/3: gather + dual GEMM (FFMA2, k-major tiles) ------
// grid 512, block 256, 64 points per block. dyn smem 86016 B.
// As/Xs are k-major [128][KP] (KP=68 keeps 16B row alignment: 68*4=272=16*17),
// so the 8 activation rows a warp needs per k are 2 broadcast LDS.128 loads.
#define KP 68

template <bool RELU>
__global__ __launch_bounds__(256) void layer_kernel(const float* __restrict__ xin,
                                                    const float* __restrict__ WrT,
                                                    const float* __restrict__ bvec,
                                                    const float* __restrict__ WsT,
                                                    float* __restrict__ xout) {
    extern __shared__ float smf[];
    float* As   = smf;                     // [128][KP] neighbor-sum, k-major
    float* Xs   = smf + 128 * KP;          // [128][KP] self features, k-major
    float* Wr_s = smf + 2 * 128 * KP;      // [16][128]
    float* Ws_s = Wr_s + 16 * HH;          // [16][128]

    const int tid = threadIdx.x;
    const int P0 = blockIdx.x * 64;
    const int base = (P0 >> 11) << 11;

    // ---- gather phase: 4 threads per point, each owns 32 dims ----
    {
        const int p = tid >> 2, c = tid & 3;
        const float4* xr = (const float4*)(xin + ((size_t)P0 + p) * HH + c * 32);
        float4 acc[8];
#pragma unroll
        for (int q = 0; q < 8; q++) {
            float4 v = xr[q];
            const int k = c * 32 + q * 4;
            Xs[(k + 0) * KP + p] = v.x;
            Xs[(k + 1) * KP + p] = v.y;
            Xs[(k + 2) * KP + p] = v.z;
            Xs[(k + 3) * KP + p] = v.w;
            acc[q] = make_float4(0.f, 0.f, 0.f, 0.f);
        }
        const int* nb = g_nbr + ((size_t)P0 + p) * KNN;
        for (int n = 0; n < KNN; n++) {
            int j = nb[n];
            const float4* ar = (const float4*)(xin + ((size_t)base + j) * HH + c * 32);
#pragma unroll
            for (int q = 0; q < 8; q++) {
                float4 v = ar[q];
                acc[q].x += v.x; acc[q].y += v.y; acc[q].z += v.z; acc[q].w += v.w;
            }
        }
#pragma unroll
        for (int q = 0; q < 8; q++) {
            const int k = c * 32 + q * 4;
            As[(k + 0) * KP + p] = acc[q].x;
            As[(k + 1) * KP + p] = acc[q].y;
            As[(k + 2) * KP + p] = acc[q].z;
            As[(k + 3) * KP + p] = acc[q].w;
        }
    }

    // ---- GEMM phase: warp owns 8 rows (m), lane owns 4 cols (h) ----
    const int warp = tid >> 5, lane = tid & 31;
    const int m0 = warp * 8, h0 = lane * 4;

    unsigned long long acc2[4][4];   // [m-pair][h]: rows (m0+2i, m0+2i+1) packed
#pragma unroll
    for (int i = 0; i < 4; i++)
#pragma unroll
        for (int j = 0; j < 4; j++) acc2[i][j] = 0ULL;

    for (int k0 = 0; k0 < HH; k0 += 16) {
        __syncthreads();   // also covers gather -> first compute
        {
            const float4* s1 = (const float4*)(WrT + (size_t)k0 * HH);
            const float4* s2 = (const float4*)(WsT + (size_t)k0 * HH);
            ((float4*)Wr_s)[tid] = s1[tid]; ((float4*)Wr_s)[tid + 256] = s1[tid + 256];
            ((float4*)Ws_s)[tid] = s2[tid]; ((float4*)Ws_s)[tid + 256] = s2[tid + 256];
        }
        __syncthreads();
#pragma unroll
        for (int kk = 0; kk < 16; kk++) {
            const int k = k0 + kk;
            // 8 activation rows = 2 broadcast LDS.128 each for As and Xs
            const ulonglong2* ap = (const ulonglong2*)(As + k * KP + m0);
            const ulonglong2* xp = (const ulonglong2*)(Xs + k * KP + m0);
            ulonglong2 av0 = ap[0], av1 = ap[1];
            ulonglong2 xv0 = xp[0], xv1 = xp[1];
            unsigned long long a2[4] = {av0.x, av0.y, av1.x, av1.y};
            unsigned long long x2[4] = {xv0.x, xv0.y, xv1.x, xv1.y};

            float4 wr = *(const float4*)(Wr_s + kk * HH + h0);
            float4 ws = *(const float4*)(Ws_s + kk * HH + h0);
            unsigned long long wr2[4], ws2[4];
            wr2[0] = pk2(wr.x, wr.x); wr2[1] = pk2(wr.y, wr.y);
            wr2[2] = pk2(wr.z, wr.z); wr2[3] = pk2(wr.w, wr.w);
            ws2[0] = pk2(ws.x, ws.x); ws2[1] = pk2(ws.y, ws.y);
            ws2[2] = pk2(ws.z, ws.z); ws2[3] = pk2(ws.w, ws.w);
#pragma unroll
            for (int i = 0; i < 4; i++)
#pragma unroll
                for (int j = 0; j < 4; j++) {
                    acc2[i][j] = fma2(a2[i], wr2[j], acc2[i][j]);
                    acc2[i][j] = fma2(x2[i], ws2[j], acc2[i][j]);
                }
        }
    }

    // ---- epilogue: + bias, optional relu, vectorized row stores ----
    const float4 bv = *(const float4*)(bvec + h0);
    const float* bf = (const float*)&bv;
#pragma unroll
    for (int i = 0; i < 4; i++) {
        float lo[4], hi[4];
#pragma unroll
        for (int j = 0; j < 4; j++) upk2(acc2[i][j], lo[j], hi[j]);
        float4 o0, o1;
        float* o0f = (float*)&o0; float* o1f = (float*)&o1;
#pragma unroll
        for (int j = 0; j < 4; j++) {
            float v0 = lo[j] + bf[j];
            float v1 = hi[j] + bf[j];
            if (RELU) { v0 = fmaxf(v0, 0.0f); v1 = fmaxf(v1, 0.0f); }
            o0f[j] = v0; o1f[j] = v1;
        }
        const size_t r0 = (size_t)P0 + m0 + 2 * i;
        *(float4*)(xout + r0 * HH + h0)       = o0;
        *(float4*)(xout + (r0 + 1) * HH + h0) = o1;
    }
}

// ---------------- launch: bind inputs BY SIZE (order-robust) ----------------
extern "C" void kernel_launch(void* const* d_in, const int* in_sizes, int n_in,
                              void* d_out, int out_size) {
    const float* pts = nullptr;
    const float* w3[2]  = {nullptr, nullptr};           int n3 = 0;
    const float* wH[4]  = {nullptr, nullptr, nullptr, nullptr}; int nH = 0;
    const float* bs[3]  = {nullptr, nullptr, nullptr};  int nb_ = 0;
    for (int i = 0; i < n_in; i++) {
        const int sz = in_sizes[i];
        const float* p = (const float*)d_in[i];
        if (sz == BB * NN * 3)      pts = p;
        else if (sz == HH * 3)      { if (n3 < 2) w3[n3++] = p; }
        else if (sz == HH * HH)     { if (nH < 4) wH[nH++] = p; }
        else if (sz == HH)          { if (nb_ < 3) bs[nb_++] = p; }
    }
    const float* W1r = w3[0];  const float* W1s = w3[1];
    const float* W2r = wH[0];  const float* W2s = wH[1];
    const float* W3r = wH[2];  const float* W3s = wH[3];
    const float* b1  = bs[0];  const float* b2  = bs[1];  const float* b3 = bs[2];
    float* out = (float*)d_out;

    const int SMEM = (2 * 128 * KP + 2 * 16 * HH) * (int)sizeof(float);  // 86016
    cudaFuncSetAttribute(layer_kernel<true>,  cudaFuncAttributeMaxDynamicSharedMemorySize, SMEM);
    cudaFuncSetAttribute(layer_kernel<false>, cudaFuncAttributeMaxDynamicSharedMemorySize, SMEM);

    float *h1, *h2, *wt;
    cudaGetSymbolAddress((void**)&h1, g_h1);
    cudaGetSymbolAddress((void**)&h2, g_h2);
    cudaGetSymbolAddress((void**)&wt, g_WT);

    transpose_kernel<<<dim3(64, 4), 256>>>(W2r, W2s, W3r, W3s);
    knn_split_kernel<<<dim3(16, NSPLIT, 16), 128>>>(pts);
    knn_merge_kernel<<<128, 256>>>();
    layer1_kernel<<<128, 256>>>(pts, W1r, b1, W1s);
    layer_kernel<true><<<512, 256, SMEM>>>(h1, wt, b2, wt + HH * HH, h2);
    layer_kernel<false><<<512, 256, SMEM>>>(h2, wt + 2 * HH * HH, b3, wt + 3 * HH * HH, out);
}